// round 5
// baseline (speedup 1.0000x reference)
#include <cuda_runtime.h>
#include <cuda_fp16.h>
#include <cstdint>

#define NTOK 8192
#define DIMC 1024
#define HIDC 4096
#define NEXP 8
#define BM 128
#define BK 32
#define MAXT 72

// ---------------- persistent device scratch ----------------
__device__ int g_order[NTOK];
__device__ int g_tile_expert[MAXT];
__device__ int g_tile_row0[MAXT];
__device__ int g_tile_rows[MAXT];
__device__ int g_ntiles;
__device__ __half g_hbuf[(size_t)(NTOK + BM) * HIDC];  // zero-init pad rows

// ---------------- routing ----------------
__global__ void route_kernel(const int* __restrict__ rm) {
    __shared__ int cnt[NEXP], off[NEXP], cur[NEXP];
    int tid = threadIdx.x;
    if (tid < NEXP) cnt[tid] = 0;
    __syncthreads();
    for (int i = tid; i < NTOK; i += blockDim.x) atomicAdd(&cnt[rm[i]], 1);
    __syncthreads();
    if (tid == 0) {
        int run = 0, nt = 0;
        for (int e = 0; e < NEXP; e++) {
            off[e] = run;
            int rem = cnt[e], r = run;
            while (rem > 0) {
                g_tile_expert[nt] = e;
                g_tile_row0[nt] = r;
                g_tile_rows[nt] = rem < BM ? rem : BM;
                r += BM; rem -= BM; nt++;
            }
            run += cnt[e];
        }
        g_ntiles = nt;
    }
    __syncthreads();
    if (tid < NEXP) cur[tid] = off[tid];
    __syncthreads();
    for (int i = tid; i < NTOK; i += blockDim.x) {
        int p = atomicAdd(&cur[rm[i]], 1);
        g_order[p] = i;
    }
}

// ---------------- helpers ----------------
__device__ __forceinline__ uint32_t su32(const void* p) {
    uint32_t a;
    asm("{ .reg .u64 t; cvta.to.shared.u64 t, %1; cvt.u32.u64 %0, t; }" : "=r"(a) : "l"(p));
    return a;
}
__device__ __forceinline__ void ldsm4(uint32_t r[4], uint32_t a) {
    asm volatile("ldmatrix.sync.aligned.m8n8.x4.shared.b16 {%0,%1,%2,%3}, [%4];"
                 : "=r"(r[0]), "=r"(r[1]), "=r"(r[2]), "=r"(r[3]) : "r"(a));
}
__device__ __forceinline__ void ldsm4t(uint32_t r[4], uint32_t a) {
    asm volatile("ldmatrix.sync.aligned.m8n8.x4.trans.shared.b16 {%0,%1,%2,%3}, [%4];"
                 : "=r"(r[0]), "=r"(r[1]), "=r"(r[2]), "=r"(r[3]) : "r"(a));
}
__device__ __forceinline__ void mma16816(float c[4], const uint32_t a[4], const uint32_t* b) {
    asm volatile(
        "mma.sync.aligned.m16n8k16.row.col.f32.f16.f16.f32 "
        "{%0,%1,%2,%3}, {%4,%5,%6,%7}, {%8,%9}, {%0,%1,%2,%3};"
        : "+f"(c[0]), "+f"(c[1]), "+f"(c[2]), "+f"(c[3])
        : "r"(a[0]), "r"(a[1]), "r"(a[2]), "r"(a[3]), "r"(b[0]), "r"(b[1]));
}
__device__ __forceinline__ uint32_t f2h2(float a, float b) {
    __half2 h = __floats2half2_rn(a, b);
    return *(uint32_t*)&h;
}
__device__ __forceinline__ uint4 pack8(const float4& u, const float4& v) {
    uint4 o;
    o.x = f2h2(u.x, u.y); o.y = f2h2(u.z, u.w);
    o.z = f2h2(v.x, v.y); o.w = f2h2(v.z, v.w);
    return o;
}

// ---------------------------------------------------------------------------
// GEMM1: h = silu(X@Wg+bg) * (X@Wi+bi); block 128M x 64N, both matrices.
// 8 warps = 2M x 4N, warp tile 64x16 per matrix. fp16 MMA m16n8k16.
// ---------------------------------------------------------------------------
__global__ void __launch_bounds__(256) gemm1_f16(
    const float* __restrict__ x,
    const float* __restrict__ Wg, const float* __restrict__ bg,
    const float* __restrict__ Wi, const float* __restrict__ bi)
{
    int mt = blockIdx.x;
    if (mt >= g_ntiles) return;
    int e = g_tile_expert[mt], row0 = g_tile_row0[mt], rows = g_tile_rows[mt];
    int n0 = blockIdx.y * 64;

    __shared__ __half As[2][128][40];
    __shared__ __half Bg[2][32][72];
    __shared__ __half Bi[2][32][72];

    int tid = threadIdx.x, lane = tid & 31, wid = tid >> 5;
    int wm = wid & 1, wn = wid >> 1;
    int gq = lane >> 2, q = lane & 3;

    float cg[4][2][4], ci[4][2][4];
#pragma unroll
    for (int i = 0; i < 4; i++)
#pragma unroll
        for (int j = 0; j < 2; j++)
#pragma unroll
            for (int k = 0; k < 4; k++) { cg[i][j][k] = 0.f; ci[i][j][k] = 0.f; }

    // A: thread -> row r = tid>>1, halves cb..cb+15 (cb = (tid&1)*16)
    int ar = tid >> 1, acb = (tid & 1) * 16;
    int gi = row0 + ar; if (gi > NTOK - 1) gi = NTOK - 1;
    const float* xr = x + (size_t)g_order[gi] * DIMC + acb;
    // B: thread -> k-row kr = tid>>3, n-cols nb..nb+7 (nb = (tid&7)*8)
    int bkr = tid >> 3, bnb = (tid & 7) * 8;
    const float* wgp = Wg + (size_t)e * DIMC * HIDC + (size_t)bkr * HIDC + n0 + bnb;
    const float* wip = Wi + (size_t)e * DIMC * HIDC + (size_t)bkr * HIDC + n0 + bnb;

    float4 av[4], gv[2], iv[2];
    const int NKT = DIMC / BK;  // 32

    // prologue: tile 0
#pragma unroll
    for (int j = 0; j < 4; j++) av[j] = *(const float4*)(xr + j * 4);
#pragma unroll
    for (int j = 0; j < 2; j++) {
        gv[j] = *(const float4*)(wgp + j * 4);
        iv[j] = *(const float4*)(wip + j * 4);
    }
    *(uint4*)&As[0][ar][acb]     = pack8(av[0], av[1]);
    *(uint4*)&As[0][ar][acb + 8] = pack8(av[2], av[3]);
    *(uint4*)&Bg[0][bkr][bnb] = pack8(gv[0], gv[1]);
    *(uint4*)&Bi[0][bkr][bnb] = pack8(iv[0], iv[1]);
    __syncthreads();

    for (int kt = 0; kt < NKT; kt++) {
        int cur = kt & 1, nxt = cur ^ 1;
        bool more = (kt + 1) < NKT;
        if (more) {
            int k0 = (kt + 1) * BK;
#pragma unroll
            for (int j = 0; j < 4; j++) av[j] = *(const float4*)(xr + k0 + j * 4);
#pragma unroll
            for (int j = 0; j < 2; j++) {
                gv[j] = *(const float4*)(wgp + (size_t)k0 * HIDC + j * 4);
                iv[j] = *(const float4*)(wip + (size_t)k0 * HIDC + j * 4);
            }
        }
        // compute on cur
#pragma unroll
        for (int ks = 0; ks < 2; ks++) {
            uint32_t af[4][4], bgf[4], bif[4];
            int arow = wm * 64 + (lane & 15);
            int acol = ks * 16 + (lane >> 4) * 8;
#pragma unroll
            for (int mf = 0; mf < 4; mf++)
                ldsm4(af[mf], su32(&As[cur][arow + mf * 16][acol]));
            int bkrow = ks * 16 + (lane & 15);
            int bncol = wn * 16 + (lane >> 4) * 8;
            ldsm4t(bgf, su32(&Bg[cur][bkrow][bncol]));
            ldsm4t(bif, su32(&Bi[cur][bkrow][bncol]));
#pragma unroll
            for (int mf = 0; mf < 4; mf++) {
                mma16816(cg[mf][0], af[mf], bgf + 0);
                mma16816(cg[mf][1], af[mf], bgf + 2);
                mma16816(ci[mf][0], af[mf], bif + 0);
                mma16816(ci[mf][1], af[mf], bif + 2);
            }
        }
        if (more) {
            *(uint4*)&As[nxt][ar][acb]     = pack8(av[0], av[1]);
            *(uint4*)&As[nxt][ar][acb + 8] = pack8(av[2], av[3]);
            *(uint4*)&Bg[nxt][bkr][bnb] = pack8(gv[0], gv[1]);
            *(uint4*)&Bi[nxt][bkr][bnb] = pack8(iv[0], iv[1]);
        }
        __syncthreads();
    }

    // epilogue: silu(g)*(v) -> g_hbuf (fp16, sorted rows)
    const float* bgp = bg + e * HIDC + n0;
    const float* bip = bi + e * HIDC + n0;
#pragma unroll
    for (int mf = 0; mf < 4; mf++) {
        int rl = wm * 64 + mf * 16 + gq;
#pragma unroll
        for (int nf = 0; nf < 2; nf++) {
            int col = wn * 16 + nf * 8 + q * 2;
            float bg0 = bgp[col], bg1 = bgp[col + 1];
            float bi0 = bip[col], bi1 = bip[col + 1];
            if (rl < rows) {
                float g0 = cg[mf][nf][0] + bg0, g1 = cg[mf][nf][1] + bg1;
                float v0 = ci[mf][nf][0] + bi0, v1 = ci[mf][nf][1] + bi1;
                float h0 = g0 * v0 / (1.f + __expf(-g0));
                float h1 = g1 * v1 / (1.f + __expf(-g1));
                *(__half2*)&g_hbuf[(size_t)(row0 + rl) * HIDC + n0 + col] =
                    __floats2half2_rn(h0, h1);
            }
            if (rl + 8 < rows) {
                float g0 = cg[mf][nf][2] + bg0, g1 = cg[mf][nf][3] + bg1;
                float v0 = ci[mf][nf][2] + bi0, v1 = ci[mf][nf][3] + bi1;
                float h0 = g0 * v0 / (1.f + __expf(-g0));
                float h1 = g1 * v1 / (1.f + __expf(-g1));
                *(__half2*)&g_hbuf[(size_t)(row0 + rl + 8) * HIDC + n0 + col] =
                    __floats2half2_rn(h0, h1);
            }
        }
    }
}

// ---------------------------------------------------------------------------
// GEMM2: out[tok] = h @ Wo + bo; block 128M x 128N, warp 64x32, scatter store.
// ---------------------------------------------------------------------------
__global__ void __launch_bounds__(256) gemm2_f16(
    const float* __restrict__ Wo, const float* __restrict__ bo, float* __restrict__ out)
{
    int mt = blockIdx.x;
    if (mt >= g_ntiles) return;
    int e = g_tile_expert[mt], row0 = g_tile_row0[mt], rows = g_tile_rows[mt];
    int n0 = blockIdx.y * 128;

    __shared__ __half As[2][128][40];
    __shared__ __half Bs[2][32][136];

    int tid = threadIdx.x, lane = tid & 31, wid = tid >> 5;
    int wm = wid & 1, wn = wid >> 1;
    int gq = lane >> 2, q = lane & 3;

    float c[4][4][4];
#pragma unroll
    for (int i = 0; i < 4; i++)
#pragma unroll
        for (int j = 0; j < 4; j++)
#pragma unroll
            for (int k = 0; k < 4; k++) c[i][j][k] = 0.f;

    int ar = tid >> 1, acb = (tid & 1) * 16;
    const __half* hr = g_hbuf + (size_t)(row0 + ar) * HIDC + acb;
    int bkr = tid >> 3, bnb = (tid & 7) * 16;
    const float* wop = Wo + (size_t)e * HIDC * DIMC + (size_t)bkr * DIMC + n0 + bnb;

    uint4 av[2];
    float4 bv[4];
    const int NKT = HIDC / BK;  // 128

    // prologue
    av[0] = *(const uint4*)(hr);
    av[1] = *(const uint4*)(hr + 8);
#pragma unroll
    for (int j = 0; j < 4; j++) bv[j] = *(const float4*)(wop + j * 4);
    *(uint4*)&As[0][ar][acb]     = av[0];
    *(uint4*)&As[0][ar][acb + 8] = av[1];
    *(uint4*)&Bs[0][bkr][bnb]     = pack8(bv[0], bv[1]);
    *(uint4*)&Bs[0][bkr][bnb + 8] = pack8(bv[2], bv[3]);
    __syncthreads();

    for (int kt = 0; kt < NKT; kt++) {
        int cur = kt & 1, nxt = cur ^ 1;
        bool more = (kt + 1) < NKT;
        if (more) {
            int k0 = (kt + 1) * BK;
            av[0] = *(const uint4*)(hr + k0);
            av[1] = *(const uint4*)(hr + k0 + 8);
#pragma unroll
            for (int j = 0; j < 4; j++)
                bv[j] = *(const float4*)(wop + (size_t)k0 * DIMC + j * 4);
        }
#pragma unroll
        for (int ks = 0; ks < 2; ks++) {
            uint32_t af[4][4], bf[2][4];
            int arow = wm * 64 + (lane & 15);
            int acol = ks * 16 + (lane >> 4) * 8;
#pragma unroll
            for (int mf = 0; mf < 4; mf++)
                ldsm4(af[mf], su32(&As[cur][arow + mf * 16][acol]));
            int bkrow = ks * 16 + (lane & 15);
#pragma unroll
            for (int h = 0; h < 2; h++) {
                int bncol = wn * 32 + h * 16 + (lane >> 4) * 8;
                ldsm4t(bf[h], su32(&Bs[cur][bkrow][bncol]));
            }
#pragma unroll
            for (int mf = 0; mf < 4; mf++) {
                mma16816(c[mf][0], af[mf], bf[0] + 0);
                mma16816(c[mf][1], af[mf], bf[0] + 2);
                mma16816(c[mf][2], af[mf], bf[1] + 0);
                mma16816(c[mf][3], af[mf], bf[1] + 2);
            }
        }
        if (more) {
            *(uint4*)&As[nxt][ar][acb]     = av[0];
            *(uint4*)&As[nxt][ar][acb + 8] = av[1];
            *(uint4*)&Bs[nxt][bkr][bnb]     = pack8(bv[0], bv[1]);
            *(uint4*)&Bs[nxt][bkr][bnb + 8] = pack8(bv[2], bv[3]);
        }
        __syncthreads();
    }

    // epilogue: scatter out[tok] = c + bo
    const float* bop = bo + e * DIMC + n0;
#pragma unroll
    for (int mf = 0; mf < 4; mf++) {
        int rl = wm * 64 + mf * 16 + gq;
        int tok0 = (rl < rows) ? g_order[row0 + rl] : -1;
        int tok1 = (rl + 8 < rows) ? g_order[row0 + rl + 8] : -1;
#pragma unroll
        for (int nf = 0; nf < 4; nf++) {
            int col = wn * 32 + nf * 8 + q * 2;
            float b0 = bop[col], b1 = bop[col + 1];
            if (tok0 >= 0)
                *(float2*)&out[(size_t)tok0 * DIMC + n0 + col] =
                    make_float2(c[mf][nf][0] + b0, c[mf][nf][1] + b1);
            if (tok1 >= 0)
                *(float2*)&out[(size_t)tok1 * DIMC + n0 + col] =
                    make_float2(c[mf][nf][2] + b0, c[mf][nf][3] + b1);
        }
    }
}

// ---------------------------------------------------------------------------
extern "C" void kernel_launch(void* const* d_in, const int* in_sizes, int n_in,
                              void* d_out, int out_size) {
    const float* x   = (const float*)d_in[0];
    const int*   rm  = (const int*)d_in[1];
    const float* Win = (const float*)d_in[2];
    const float* bin = (const float*)d_in[3];
    const float* Wgt = (const float*)d_in[4];
    const float* bgt = (const float*)d_in[5];
    const float* Wo  = (const float*)d_in[6];
    const float* bo  = (const float*)d_in[7];
    float* out = (float*)d_out;

    route_kernel<<<1, 256>>>(rm);
    gemm1_f16<<<dim3(MAXT, HIDC / 64), 256>>>(x, Wgt, bgt, Win, bin);
    gemm2_f16<<<dim3(MAXT, DIMC / 128), 256>>>(Wo, bo, out);
}

// round 6
// speedup vs baseline: 3.0510x; 3.0510x over previous
#include <cuda_runtime.h>
#include <cuda_fp16.h>
#include <cstdint>

#define NTOK 8192
#define DIMC 1024
#define HIDC 4096
#define NEXP 8
#define BM 128
#define MAXT 72
#define WSZ (NEXP * DIMC * HIDC)

// ---------------- persistent device scratch ----------------
__device__ int g_order[NTOK];
__device__ int g_tile_expert[MAXT];
__device__ int g_tile_row0[MAXT];
__device__ int g_tile_rows[MAXT];
__device__ int g_ntiles;
__device__ __half g_hbuf[(size_t)(NTOK + BM) * HIDC];  // zero-init pad rows
__device__ __half g_whg[WSZ];
__device__ __half g_whi[WSZ];
__device__ __half g_who[WSZ];
__device__ __half g_xh[NTOK * DIMC];

// ---------------- routing ----------------
__global__ void route_kernel(const int* __restrict__ rm) {
    __shared__ int cnt[NEXP], off[NEXP], cur[NEXP];
    int tid = threadIdx.x;
    if (tid < NEXP) cnt[tid] = 0;
    __syncthreads();
    for (int i = tid; i < NTOK; i += blockDim.x) atomicAdd(&cnt[rm[i]], 1);
    __syncthreads();
    if (tid == 0) {
        int run = 0, nt = 0;
        for (int e = 0; e < NEXP; e++) {
            off[e] = run;
            int rem = cnt[e], r = run;
            while (rem > 0) {
                g_tile_expert[nt] = e;
                g_tile_row0[nt] = r;
                g_tile_rows[nt] = rem < BM ? rem : BM;
                r += BM; rem -= BM; nt++;
            }
            run += cnt[e];
        }
        g_ntiles = nt;
    }
    __syncthreads();
    if (tid < NEXP) cur[tid] = off[tid];
    __syncthreads();
    for (int i = tid; i < NTOK; i += blockDim.x) {
        int p = atomicAdd(&cur[rm[i]], 1);
        g_order[p] = i;
    }
}

// ---------------- helpers ----------------
__device__ __forceinline__ uint32_t su32(const void* p) {
    uint32_t a;
    asm("{ .reg .u64 t; cvta.to.shared.u64 t, %1; cvt.u32.u64 %0, t; }" : "=r"(a) : "l"(p));
    return a;
}
__device__ __forceinline__ void ldsm4(uint32_t r[4], uint32_t a) {
    asm volatile("ldmatrix.sync.aligned.m8n8.x4.shared.b16 {%0,%1,%2,%3}, [%4];"
                 : "=r"(r[0]), "=r"(r[1]), "=r"(r[2]), "=r"(r[3]) : "r"(a));
}
__device__ __forceinline__ void ldsm4t(uint32_t r[4], uint32_t a) {
    asm volatile("ldmatrix.sync.aligned.m8n8.x4.trans.shared.b16 {%0,%1,%2,%3}, [%4];"
                 : "=r"(r[0]), "=r"(r[1]), "=r"(r[2]), "=r"(r[3]) : "r"(a));
}
__device__ __forceinline__ void mma16816(float c[4], const uint32_t a[4], const uint32_t* b) {
    asm volatile(
        "mma.sync.aligned.m16n8k16.row.col.f32.f16.f16.f32 "
        "{%0,%1,%2,%3}, {%4,%5,%6,%7}, {%8,%9}, {%0,%1,%2,%3};"
        : "+f"(c[0]), "+f"(c[1]), "+f"(c[2]), "+f"(c[3])
        : "r"(a[0]), "r"(a[1]), "r"(a[2]), "r"(a[3]), "r"(b[0]), "r"(b[1]));
}
__device__ __forceinline__ uint32_t f2h2(float a, float b) {
    __half2 h = __floats2half2_rn(a, b);
    return *(uint32_t*)&h;
}
#define CP16(dst, src) asm volatile("cp.async.cg.shared.global [%0], [%1], 16;" :: "r"(dst), "l"(src))
#define CPCOMMIT() asm volatile("cp.async.commit_group;" ::: "memory")
#define CPWAIT2() asm volatile("cp.async.wait_group 2;" ::: "memory")

// ---------------- fp32 -> fp16 conversion ----------------
__global__ void __launch_bounds__(256) cvt_kernel(
    const float* __restrict__ Wg, const float* __restrict__ Wi,
    const float* __restrict__ Wo, const float* __restrict__ x)
{
    size_t stride = (size_t)gridDim.x * blockDim.x;
    size_t t0 = (size_t)blockIdx.x * blockDim.x + threadIdx.x;
    for (size_t i = t0; i < WSZ / 8; i += stride) {
        float4 a, b; uint4 o;
        a = ((const float4*)Wg)[i * 2]; b = ((const float4*)Wg)[i * 2 + 1];
        o.x = f2h2(a.x, a.y); o.y = f2h2(a.z, a.w); o.z = f2h2(b.x, b.y); o.w = f2h2(b.z, b.w);
        ((uint4*)g_whg)[i] = o;
        a = ((const float4*)Wi)[i * 2]; b = ((const float4*)Wi)[i * 2 + 1];
        o.x = f2h2(a.x, a.y); o.y = f2h2(a.z, a.w); o.z = f2h2(b.x, b.y); o.w = f2h2(b.z, b.w);
        ((uint4*)g_whi)[i] = o;
        a = ((const float4*)Wo)[i * 2]; b = ((const float4*)Wo)[i * 2 + 1];
        o.x = f2h2(a.x, a.y); o.y = f2h2(a.z, a.w); o.z = f2h2(b.x, b.y); o.w = f2h2(b.z, b.w);
        ((uint4*)g_who)[i] = o;
    }
    for (size_t i = t0; i < (size_t)NTOK * DIMC / 8; i += stride) {
        float4 a = ((const float4*)x)[i * 2], b = ((const float4*)x)[i * 2 + 1];
        uint4 o;
        o.x = f2h2(a.x, a.y); o.y = f2h2(a.z, a.w); o.z = f2h2(b.x, b.y); o.w = f2h2(b.z, b.w);
        ((uint4*)g_xh)[i] = o;
    }
}

// ---------------------------------------------------------------------------
// GEMM1: h = silu(X@Wg+bg)*(X@Wi+bi); 128M x 64N x both; BK=32, 4-stage cp.async.
// Stage layout (16KB): A[128x32h swz] @0, Bg[32x64h swz] @8192, Bi @12288.
// ---------------------------------------------------------------------------
__global__ void __launch_bounds__(256, 2) gemm1_f16(
    const float* __restrict__ bg, const float* __restrict__ bi)
{
    int mt = blockIdx.x;
    if (mt >= g_ntiles) return;
    int e = g_tile_expert[mt], row0 = g_tile_row0[mt], rows = g_tile_rows[mt];
    int n0 = blockIdx.y * 64;
    extern __shared__ char smem[];
    uint32_t sb = su32(smem);

    int tid = threadIdx.x, lane = tid & 31, wid = tid >> 5;
    int wm = wid & 1, wn = wid >> 1;
    int gq = lane >> 2, q = lane & 3;

    float cg[4][2][4], ci[4][2][4];
#pragma unroll
    for (int i = 0; i < 4; i++)
#pragma unroll
        for (int j = 0; j < 2; j++)
#pragma unroll
            for (int k = 0; k < 4; k++) { cg[i][j][k] = 0.f; ci[i][j][k] = 0.f; }

    // loader mappings
    const __half* srcA[2];
    uint32_t dstA[2];
#pragma unroll
    for (int p = 0; p < 2; p++) {
        int c = tid + p * 256;
        int row = c >> 2, ch = c & 3;
        int gi = row0 + row; if (gi > NTOK - 1) gi = NTOK - 1;
        srcA[p] = g_xh + (size_t)g_order[gi] * DIMC + ch * 8;
        dstA[p] = row * 64 + ((ch ^ ((row >> 1) & 3)) << 4);
    }
    int bkk = tid >> 3, bch = tid & 7;
    const __half* srcG = g_whg + ((size_t)e * DIMC + bkk) * HIDC + n0 + bch * 8;
    const __half* srcI = g_whi + ((size_t)e * DIMC + bkk) * HIDC + n0 + bch * 8;
    uint32_t dstB = bkk * 128 + ((bch ^ (bkk & 7)) << 4);

    const int NKT = DIMC / 32;  // 32
#define G1_ISSUE(KT) do { \
    int s_ = (KT) & 3; uint32_t st_ = sb + s_ * 16384; int k0_ = (KT) * 32; \
    CP16(st_ + dstA[0], srcA[0] + k0_); \
    CP16(st_ + dstA[1], srcA[1] + k0_); \
    CP16(st_ + 8192 + dstB, srcG + (size_t)(KT) * 32 * HIDC); \
    CP16(st_ + 12288 + dstB, srcI + (size_t)(KT) * 32 * HIDC); \
} while (0)

    G1_ISSUE(0); CPCOMMIT();
    G1_ISSUE(1); CPCOMMIT();
    G1_ISSUE(2); CPCOMMIT();

    for (int kt = 0; kt < NKT; kt++) {
        CPWAIT2();
        __syncthreads();
        if (kt + 3 < NKT) G1_ISSUE(kt + 3);
        CPCOMMIT();
        uint32_t st = sb + (kt & 3) * 16384;
#pragma unroll
        for (int ks = 0; ks < 2; ks++) {
            uint32_t af[4][4], bgf[4], bif[4];
            int arow = wm * 64 + (lane & 15);
            int achk = 2 * ks + (lane >> 4);
#pragma unroll
            for (int mf = 0; mf < 4; mf++) {
                int r = arow + mf * 16;
                ldsm4(af[mf], st + r * 64 + ((achk ^ ((r >> 1) & 3)) << 4));
            }
            int bkr = ks * 16 + (lane & 15);
            int bchk = 2 * wn + (lane >> 4);
            uint32_t boff = bkr * 128 + ((bchk ^ (bkr & 7)) << 4);
            ldsm4t(bgf, st + 8192 + boff);
            ldsm4t(bif, st + 12288 + boff);
#pragma unroll
            for (int mf = 0; mf < 4; mf++) {
                mma16816(cg[mf][0], af[mf], bgf + 0);
                mma16816(cg[mf][1], af[mf], bgf + 2);
                mma16816(ci[mf][0], af[mf], bif + 0);
                mma16816(ci[mf][1], af[mf], bif + 2);
            }
        }
    }

    // epilogue: silu(g)*(v) -> g_hbuf (fp16, sorted rows)
    const float* bgp = bg + e * HIDC + n0;
    const float* bip = bi + e * HIDC + n0;
#pragma unroll
    for (int mf = 0; mf < 4; mf++) {
        int rl = wm * 64 + mf * 16 + gq;
#pragma unroll
        for (int nf = 0; nf < 2; nf++) {
            int col = wn * 16 + nf * 8 + q * 2;
            float bg0 = bgp[col], bg1 = bgp[col + 1];
            float bi0 = bip[col], bi1 = bip[col + 1];
            if (rl < rows) {
                float g0 = cg[mf][nf][0] + bg0, g1 = cg[mf][nf][1] + bg1;
                float v0 = ci[mf][nf][0] + bi0, v1 = ci[mf][nf][1] + bi1;
                *(__half2*)&g_hbuf[(size_t)(row0 + rl) * HIDC + n0 + col] =
                    __floats2half2_rn(g0 * v0 / (1.f + __expf(-g0)),
                                      g1 * v1 / (1.f + __expf(-g1)));
            }
            if (rl + 8 < rows) {
                float g0 = cg[mf][nf][2] + bg0, g1 = cg[mf][nf][3] + bg1;
                float v0 = ci[mf][nf][2] + bi0, v1 = ci[mf][nf][3] + bi1;
                *(__half2*)&g_hbuf[(size_t)(row0 + rl + 8) * HIDC + n0 + col] =
                    __floats2half2_rn(g0 * v0 / (1.f + __expf(-g0)),
                                      g1 * v1 / (1.f + __expf(-g1)));
            }
        }
    }
}

// ---------------------------------------------------------------------------
// GEMM2: out[tok] = h @ Wo + bo; 128M x 128N; BK=32, 4-stage cp.async.
// Stage layout (16KB): A[128x32h swz] @0, B[32x128h swz] @8192.
// ---------------------------------------------------------------------------
__global__ void __launch_bounds__(256, 2) gemm2_f16(
    const float* __restrict__ bo, float* __restrict__ out)
{
    int mt = blockIdx.x;
    if (mt >= g_ntiles) return;
    int e = g_tile_expert[mt], row0 = g_tile_row0[mt], rows = g_tile_rows[mt];
    int n0 = blockIdx.y * 128;
    extern __shared__ char smem[];
    uint32_t sb = su32(smem);

    int tid = threadIdx.x, lane = tid & 31, wid = tid >> 5;
    int wm = wid & 1, wn = wid >> 1;
    int gq = lane >> 2, q = lane & 3;

    float c[4][4][4];
#pragma unroll
    for (int i = 0; i < 4; i++)
#pragma unroll
        for (int j = 0; j < 4; j++)
#pragma unroll
            for (int k = 0; k < 4; k++) c[i][j][k] = 0.f;

    const __half* srcA[2];
    uint32_t dstA[2];
#pragma unroll
    for (int p = 0; p < 2; p++) {
        int cc = tid + p * 256;
        int row = cc >> 2, ch = cc & 3;
        srcA[p] = g_hbuf + (size_t)(row0 + row) * HIDC + ch * 8;
        dstA[p] = row * 64 + ((ch ^ ((row >> 1) & 3)) << 4);
    }
    const __half* srcB[2];
    uint32_t dstB[2];
#pragma unroll
    for (int p = 0; p < 2; p++) {
        int cc = tid + p * 256;
        int kk = cc >> 4, ch = cc & 15;
        srcB[p] = g_who + ((size_t)e * HIDC + kk) * DIMC + n0 + ch * 8;
        dstB[p] = kk * 256 + ((ch ^ (kk & 7)) << 4);
    }

    const int NKT = HIDC / 32;  // 128
#define G2_ISSUE(KT) do { \
    int s_ = (KT) & 3; uint32_t st_ = sb + s_ * 16384; int k0_ = (KT) * 32; \
    CP16(st_ + dstA[0], srcA[0] + k0_); \
    CP16(st_ + dstA[1], srcA[1] + k0_); \
    CP16(st_ + 8192 + dstB[0], srcB[0] + (size_t)(KT) * 32 * DIMC); \
    CP16(st_ + 8192 + dstB[1], srcB[1] + (size_t)(KT) * 32 * DIMC); \
} while (0)

    G2_ISSUE(0); CPCOMMIT();
    G2_ISSUE(1); CPCOMMIT();
    G2_ISSUE(2); CPCOMMIT();

    for (int kt = 0; kt < NKT; kt++) {
        CPWAIT2();
        __syncthreads();
        if (kt + 3 < NKT) G2_ISSUE(kt + 3);
        CPCOMMIT();
        uint32_t st = sb + (kt & 3) * 16384;
#pragma unroll
        for (int ks = 0; ks < 2; ks++) {
            uint32_t af[4][4], bf[2][4];
            int arow = wm * 64 + (lane & 15);
            int achk = 2 * ks + (lane >> 4);
#pragma unroll
            for (int mf = 0; mf < 4; mf++) {
                int r = arow + mf * 16;
                ldsm4(af[mf], st + r * 64 + ((achk ^ ((r >> 1) & 3)) << 4));
            }
            int bkr = ks * 16 + (lane & 15);
#pragma unroll
            for (int h = 0; h < 2; h++) {
                int bchk = 4 * wn + 2 * h + (lane >> 4);
                ldsm4t(bf[h], st + 8192 + bkr * 256 + ((bchk ^ (bkr & 7)) << 4));
            }
#pragma unroll
            for (int mf = 0; mf < 4; mf++) {
                mma16816(c[mf][0], af[mf], bf[0] + 0);
                mma16816(c[mf][1], af[mf], bf[0] + 2);
                mma16816(c[mf][2], af[mf], bf[1] + 0);
                mma16816(c[mf][3], af[mf], bf[1] + 2);
            }
        }
    }

    // epilogue: scatter out[tok] = c + bo
    const float* bop = bo + e * DIMC + n0;
#pragma unroll
    for (int mf = 0; mf < 4; mf++) {
        int rl = wm * 64 + mf * 16 + gq;
        int tok0 = (rl < rows) ? g_order[row0 + rl] : -1;
        int tok1 = (rl + 8 < rows) ? g_order[row0 + rl + 8] : -1;
#pragma unroll
        for (int nf = 0; nf < 4; nf++) {
            int col = wn * 32 + nf * 8 + q * 2;
            float b0 = bop[col], b1 = bop[col + 1];
            if (tok0 >= 0)
                *(float2*)&out[(size_t)tok0 * DIMC + n0 + col] =
                    make_float2(c[mf][nf][0] + b0, c[mf][nf][1] + b1);
            if (tok1 >= 0)
                *(float2*)&out[(size_t)tok1 * DIMC + n0 + col] =
                    make_float2(c[mf][nf][2] + b0, c[mf][nf][3] + b1);
        }
    }
}

// ---------------------------------------------------------------------------
extern "C" void kernel_launch(void* const* d_in, const int* in_sizes, int n_in,
                              void* d_out, int out_size) {
    const float* x   = (const float*)d_in[0];
    const int*   rm  = (const int*)d_in[1];
    const float* Win = (const float*)d_in[2];
    const float* bin = (const float*)d_in[3];
    const float* Wgt = (const float*)d_in[4];
    const float* bgt = (const float*)d_in[5];
    const float* Wo  = (const float*)d_in[6];
    const float* bo  = (const float*)d_in[7];
    float* out = (float*)d_out;

    cudaFuncSetAttribute(gemm1_f16, cudaFuncAttributeMaxDynamicSharedMemorySize, 65536);
    cudaFuncSetAttribute(gemm2_f16, cudaFuncAttributeMaxDynamicSharedMemorySize, 65536);

    route_kernel<<<1, 256>>>(rm);
    cvt_kernel<<<2048, 256>>>(Wgt, Win, Wo, x);
    gemm1_f16<<<dim3(MAXT, HIDC / 64), 256, 65536>>>(bgt, bin);
    gemm2_f16<<<dim3(MAXT, DIMC / 128), 256, 65536>>>(bo, out);
}

// round 7
// speedup vs baseline: 3.2361x; 1.0607x over previous
#include <cuda_runtime.h>
#include <cuda_fp16.h>
#include <cstdint>

#define NTOK 8192
#define DIMC 1024
#define HIDC 4096
#define NEXP 8
#define BM 128
#define MAXT 72
#define WSZ (NEXP * DIMC * HIDC)

// ---------------- persistent device scratch ----------------
__device__ int g_order[NTOK];
__device__ int g_tile_expert[MAXT];
__device__ int g_tile_row0[MAXT];
__device__ int g_tile_rows[MAXT];
__device__ int g_ntiles;
__device__ __half g_hbuf[(size_t)(NTOK + BM) * HIDC];  // zero-init pad rows
__device__ __half g_whg[WSZ];
__device__ __half g_whi[WSZ];
__device__ __half g_who[WSZ];
__device__ __half g_xh[NTOK * DIMC];

// ---------------- helpers ----------------
__device__ __forceinline__ uint32_t su32(const void* p) {
    uint32_t a;
    asm("{ .reg .u64 t; cvta.to.shared.u64 t, %1; cvt.u32.u64 %0, t; }" : "=r"(a) : "l"(p));
    return a;
}
__device__ __forceinline__ void ldsm4(uint32_t r[4], uint32_t a) {
    asm volatile("ldmatrix.sync.aligned.m8n8.x4.shared.b16 {%0,%1,%2,%3}, [%4];"
                 : "=r"(r[0]), "=r"(r[1]), "=r"(r[2]), "=r"(r[3]) : "r"(a));
}
__device__ __forceinline__ void ldsm4t(uint32_t r[4], uint32_t a) {
    asm volatile("ldmatrix.sync.aligned.m8n8.x4.trans.shared.b16 {%0,%1,%2,%3}, [%4];"
                 : "=r"(r[0]), "=r"(r[1]), "=r"(r[2]), "=r"(r[3]) : "r"(a));
}
__device__ __forceinline__ void mma16816(float c[4], const uint32_t a[4], const uint32_t* b) {
    asm volatile(
        "mma.sync.aligned.m16n8k16.row.col.f32.f16.f16.f32 "
        "{%0,%1,%2,%3}, {%4,%5,%6,%7}, {%8,%9}, {%0,%1,%2,%3};"
        : "+f"(c[0]), "+f"(c[1]), "+f"(c[2]), "+f"(c[3])
        : "r"(a[0]), "r"(a[1]), "r"(a[2]), "r"(a[3]), "r"(b[0]), "r"(b[1]));
}
__device__ __forceinline__ uint32_t f2h2(float a, float b) {
    __half2 h = __floats2half2_rn(a, b);
    return *(uint32_t*)&h;
}
#define CP16(dst, src) asm volatile("cp.async.cg.shared.global [%0], [%1], 16;" :: "r"(dst), "l"(src))
#define CPCOMMIT() asm volatile("cp.async.commit_group;" ::: "memory")
#define CPWAIT1() asm volatile("cp.async.wait_group 1;" ::: "memory")

// ---------------- fused fp32->fp16 conversion + routing ----------------
__global__ void __launch_bounds__(256) cvt_route_kernel(
    const float* __restrict__ Wg, const float* __restrict__ Wi,
    const float* __restrict__ Wo, const float* __restrict__ x,
    const int* __restrict__ rm)
{
    __shared__ int cnt[NEXP], off[NEXP], cur[NEXP];
    int tid = threadIdx.x;
    if (blockIdx.x == gridDim.x - 1) {
        // routing block
        if (tid < NEXP) cnt[tid] = 0;
        __syncthreads();
        for (int i = tid; i < NTOK; i += blockDim.x) atomicAdd(&cnt[rm[i]], 1);
        __syncthreads();
        if (tid == 0) {
            int run = 0, nt = 0;
            for (int e = 0; e < NEXP; e++) {
                off[e] = run;
                int rem = cnt[e], r = run;
                while (rem > 0) {
                    g_tile_expert[nt] = e;
                    g_tile_row0[nt] = r;
                    g_tile_rows[nt] = rem < BM ? rem : BM;
                    r += BM; rem -= BM; nt++;
                }
                run += cnt[e];
            }
            g_ntiles = nt;
        }
        __syncthreads();
        if (tid < NEXP) cur[tid] = off[tid];
        __syncthreads();
        for (int i = tid; i < NTOK; i += blockDim.x) {
            int p = atomicAdd(&cur[rm[i]], 1);
            g_order[p] = i;
        }
        return;
    }
    size_t stride = (size_t)(gridDim.x - 1) * blockDim.x;
    size_t t0 = (size_t)blockIdx.x * blockDim.x + tid;
    for (size_t i = t0; i < WSZ / 8; i += stride) {
        float4 a, b; uint4 o;
        a = ((const float4*)Wg)[i * 2]; b = ((const float4*)Wg)[i * 2 + 1];
        o.x = f2h2(a.x, a.y); o.y = f2h2(a.z, a.w); o.z = f2h2(b.x, b.y); o.w = f2h2(b.z, b.w);
        ((uint4*)g_whg)[i] = o;
        a = ((const float4*)Wi)[i * 2]; b = ((const float4*)Wi)[i * 2 + 1];
        o.x = f2h2(a.x, a.y); o.y = f2h2(a.z, a.w); o.z = f2h2(b.x, b.y); o.w = f2h2(b.z, b.w);
        ((uint4*)g_whi)[i] = o;
        a = ((const float4*)Wo)[i * 2]; b = ((const float4*)Wo)[i * 2 + 1];
        o.x = f2h2(a.x, a.y); o.y = f2h2(a.z, a.w); o.z = f2h2(b.x, b.y); o.w = f2h2(b.z, b.w);
        ((uint4*)g_who)[i] = o;
    }
    for (size_t i = t0; i < (size_t)NTOK * DIMC / 8; i += stride) {
        float4 a = ((const float4*)x)[i * 2], b = ((const float4*)x)[i * 2 + 1];
        uint4 o;
        o.x = f2h2(a.x, a.y); o.y = f2h2(a.z, a.w); o.z = f2h2(b.x, b.y); o.w = f2h2(b.z, b.w);
        ((uint4*)g_xh)[i] = o;
    }
}

// ---------------------------------------------------------------------------
// GEMM1: h = silu(X@Wg+bg)*(X@Wi+bi); 128M x 64N x both; BK=64, 3-stage.
// Stage (32KB): A[128x64h] @0, Bg[64x64h] @16384, Bi @24576. XOR-8 swizzle.
// ---------------------------------------------------------------------------
__global__ void __launch_bounds__(256, 2) gemm1_f16(
    const float* __restrict__ bg, const float* __restrict__ bi)
{
    int mt = blockIdx.x;
    if (mt >= g_ntiles) return;
    int e = g_tile_expert[mt], row0 = g_tile_row0[mt], rows = g_tile_rows[mt];
    int n0 = blockIdx.y * 64;
    extern __shared__ char smem[];
    uint32_t sb = su32(smem);

    int tid = threadIdx.x, lane = tid & 31, wid = tid >> 5;
    int wm = wid & 1, wn = wid >> 1;
    int gq = lane >> 2, q = lane & 3;

    float cg[4][2][4], ci[4][2][4];
#pragma unroll
    for (int i = 0; i < 4; i++)
#pragma unroll
        for (int j = 0; j < 2; j++)
#pragma unroll
            for (int k = 0; k < 4; k++) { cg[i][j][k] = 0.f; ci[i][j][k] = 0.f; }

    // A loader: 128 rows x 8 chunks = 1024; 4 per thread
    const __half* srcA[4];
    uint32_t dstA[4];
#pragma unroll
    for (int p = 0; p < 4; p++) {
        int c = tid + p * 256;
        int row = c >> 3, ch = c & 7;
        int gi = row0 + row; if (gi > NTOK - 1) gi = NTOK - 1;
        srcA[p] = g_xh + (size_t)g_order[gi] * DIMC + ch * 8;
        dstA[p] = row * 128 + ((ch ^ (row & 7)) << 4);
    }
    // B loaders: 64 rows x 8 chunks = 512; 2 per thread each matrix
    const __half *srcG[2], *srcI[2];
    uint32_t dstB[2];
#pragma unroll
    for (int p = 0; p < 2; p++) {
        int c = tid + p * 256;
        int kk = c >> 3, ch = c & 7;
        srcG[p] = g_whg + ((size_t)e * DIMC + kk) * HIDC + n0 + ch * 8;
        srcI[p] = g_whi + ((size_t)e * DIMC + kk) * HIDC + n0 + ch * 8;
        dstB[p] = kk * 128 + ((ch ^ (kk & 7)) << 4);
    }

    const int NKT = DIMC / 64;  // 16
#define G1_ISSUE(KT) do { \
    uint32_t st_ = sb + ((KT) % 3) * 32768; int k0_ = (KT) * 64; \
    CP16(st_ + dstA[0], srcA[0] + k0_); \
    CP16(st_ + dstA[1], srcA[1] + k0_); \
    CP16(st_ + dstA[2], srcA[2] + k0_); \
    CP16(st_ + dstA[3], srcA[3] + k0_); \
    CP16(st_ + 16384 + dstB[0], srcG[0] + (size_t)k0_ * HIDC); \
    CP16(st_ + 16384 + dstB[1], srcG[1] + (size_t)k0_ * HIDC); \
    CP16(st_ + 24576 + dstB[0], srcI[0] + (size_t)k0_ * HIDC); \
    CP16(st_ + 24576 + dstB[1], srcI[1] + (size_t)k0_ * HIDC); \
} while (0)

    G1_ISSUE(0); CPCOMMIT();
    G1_ISSUE(1); CPCOMMIT();

    for (int kt = 0; kt < NKT; kt++) {
        CPWAIT1();
        __syncthreads();
        if (kt + 2 < NKT) G1_ISSUE(kt + 2);
        CPCOMMIT();
        uint32_t st = sb + (kt % 3) * 32768;
#pragma unroll
        for (int ks = 0; ks < 4; ks++) {
            uint32_t af[4][4], bgf[4], bif[4];
            int arow = wm * 64 + (lane & 15);
            int achk = 2 * ks + (lane >> 4);
#pragma unroll
            for (int mf = 0; mf < 4; mf++) {
                int r = arow + mf * 16;
                ldsm4(af[mf], st + r * 128 + ((achk ^ (r & 7)) << 4));
            }
            int bkr = ks * 16 + (lane & 15);
            int bchk = 2 * wn + (lane >> 4);
            uint32_t boff = bkr * 128 + ((bchk ^ (bkr & 7)) << 4);
            ldsm4t(bgf, st + 16384 + boff);
            ldsm4t(bif, st + 24576 + boff);
#pragma unroll
            for (int mf = 0; mf < 4; mf++) {
                mma16816(cg[mf][0], af[mf], bgf + 0);
                mma16816(cg[mf][1], af[mf], bgf + 2);
                mma16816(ci[mf][0], af[mf], bif + 0);
                mma16816(ci[mf][1], af[mf], bif + 2);
            }
        }
    }

    // epilogue: silu(g)*(v) -> g_hbuf (fp16, sorted rows)
    const float* bgp = bg + e * HIDC + n0;
    const float* bip = bi + e * HIDC + n0;
#pragma unroll
    for (int mf = 0; mf < 4; mf++) {
        int rl = wm * 64 + mf * 16 + gq;
#pragma unroll
        for (int nf = 0; nf < 2; nf++) {
            int col = wn * 16 + nf * 8 + q * 2;
            float bg0 = bgp[col], bg1 = bgp[col + 1];
            float bi0 = bip[col], bi1 = bip[col + 1];
            if (rl < rows) {
                float g0 = cg[mf][nf][0] + bg0, g1 = cg[mf][nf][1] + bg1;
                float v0 = ci[mf][nf][0] + bi0, v1 = ci[mf][nf][1] + bi1;
                *(__half2*)&g_hbuf[(size_t)(row0 + rl) * HIDC + n0 + col] =
                    __floats2half2_rn(g0 * v0 / (1.f + __expf(-g0)),
                                      g1 * v1 / (1.f + __expf(-g1)));
            }
            if (rl + 8 < rows) {
                float g0 = cg[mf][nf][2] + bg0, g1 = cg[mf][nf][3] + bg1;
                float v0 = ci[mf][nf][2] + bi0, v1 = ci[mf][nf][3] + bi1;
                *(__half2*)&g_hbuf[(size_t)(row0 + rl + 8) * HIDC + n0 + col] =
                    __floats2half2_rn(g0 * v0 / (1.f + __expf(-g0)),
                                      g1 * v1 / (1.f + __expf(-g1)));
            }
        }
    }
}

// ---------------------------------------------------------------------------
// GEMM2: out[tok] = h @ Wo + bo; 128M x 128N; BK=64, 3-stage.
// Stage (32KB): A[128x64h] @0, B[64x128h] @16384.
// ---------------------------------------------------------------------------
__global__ void __launch_bounds__(256, 2) gemm2_f16(
    const float* __restrict__ bo, float* __restrict__ out)
{
    int mt = blockIdx.x;
    if (mt >= g_ntiles) return;
    int e = g_tile_expert[mt], row0 = g_tile_row0[mt], rows = g_tile_rows[mt];
    int n0 = blockIdx.y * 128;
    extern __shared__ char smem[];
    uint32_t sb = su32(smem);

    int tid = threadIdx.x, lane = tid & 31, wid = tid >> 5;
    int wm = wid & 1, wn = wid >> 1;
    int gq = lane >> 2, q = lane & 3;

    float c[4][4][4];
#pragma unroll
    for (int i = 0; i < 4; i++)
#pragma unroll
        for (int j = 0; j < 4; j++)
#pragma unroll
            for (int k = 0; k < 4; k++) c[i][j][k] = 0.f;

    const __half* srcA[4];
    uint32_t dstA[4];
#pragma unroll
    for (int p = 0; p < 4; p++) {
        int cc = tid + p * 256;
        int row = cc >> 3, ch = cc & 7;
        srcA[p] = g_hbuf + (size_t)(row0 + row) * HIDC + ch * 8;
        dstA[p] = row * 128 + ((ch ^ (row & 7)) << 4);
    }
    const __half* srcB[4];
    uint32_t dstB[4];
#pragma unroll
    for (int p = 0; p < 4; p++) {
        int cc = tid + p * 256;
        int kk = cc >> 4, ch = cc & 15;
        srcB[p] = g_who + ((size_t)e * HIDC + kk) * DIMC + n0 + ch * 8;
        dstB[p] = kk * 256 + ((ch ^ (kk & 7)) << 4);
    }

    const int NKT = HIDC / 64;  // 64
#define G2_ISSUE(KT) do { \
    uint32_t st_ = sb + ((KT) % 3) * 32768; int k0_ = (KT) * 64; \
    CP16(st_ + dstA[0], srcA[0] + k0_); \
    CP16(st_ + dstA[1], srcA[1] + k0_); \
    CP16(st_ + dstA[2], srcA[2] + k0_); \
    CP16(st_ + dstA[3], srcA[3] + k0_); \
    CP16(st_ + 16384 + dstB[0], srcB[0] + (size_t)k0_ * DIMC); \
    CP16(st_ + 16384 + dstB[1], srcB[1] + (size_t)k0_ * DIMC); \
    CP16(st_ + 16384 + dstB[2], srcB[2] + (size_t)k0_ * DIMC); \
    CP16(st_ + 16384 + dstB[3], srcB[3] + (size_t)k0_ * DIMC); \
} while (0)

    G2_ISSUE(0); CPCOMMIT();
    G2_ISSUE(1); CPCOMMIT();

    for (int kt = 0; kt < NKT; kt++) {
        CPWAIT1();
        __syncthreads();
        if (kt + 2 < NKT) G2_ISSUE(kt + 2);
        CPCOMMIT();
        uint32_t st = sb + (kt % 3) * 32768;
#pragma unroll
        for (int ks = 0; ks < 4; ks++) {
            uint32_t af[4][4], bf[2][4];
            int arow = wm * 64 + (lane & 15);
            int achk = 2 * ks + (lane >> 4);
#pragma unroll
            for (int mf = 0; mf < 4; mf++) {
                int r = arow + mf * 16;
                ldsm4(af[mf], st + r * 128 + ((achk ^ (r & 7)) << 4));
            }
            int bkr = ks * 16 + (lane & 15);
#pragma unroll
            for (int h = 0; h < 2; h++) {
                int bchk = 4 * wn + 2 * h + (lane >> 4);
                ldsm4t(bf[h], st + 16384 + bkr * 256 + ((bchk ^ (bkr & 7)) << 4));
            }
#pragma unroll
            for (int mf = 0; mf < 4; mf++) {
                mma16816(c[mf][0], af[mf], bf[0] + 0);
                mma16816(c[mf][1], af[mf], bf[0] + 2);
                mma16816(c[mf][2], af[mf], bf[1] + 0);
                mma16816(c[mf][3], af[mf], bf[1] + 2);
            }
        }
    }

    // epilogue: scatter out[tok] = c + bo
    const float* bop = bo + e * DIMC + n0;
#pragma unroll
    for (int mf = 0; mf < 4; mf++) {
        int rl = wm * 64 + mf * 16 + gq;
        int tok0 = (rl < rows) ? g_order[row0 + rl] : -1;
        int tok1 = (rl + 8 < rows) ? g_order[row0 + rl + 8] : -1;
#pragma unroll
        for (int nf = 0; nf < 4; nf++) {
            int col = wn * 32 + nf * 8 + q * 2;
            float b0 = bop[col], b1 = bop[col + 1];
            if (tok0 >= 0)
                *(float2*)&out[(size_t)tok0 * DIMC + n0 + col] =
                    make_float2(c[mf][nf][0] + b0, c[mf][nf][1] + b1);
            if (tok1 >= 0)
                *(float2*)&out[(size_t)tok1 * DIMC + n0 + col] =
                    make_float2(c[mf][nf][2] + b0, c[mf][nf][3] + b1);
        }
    }
}

// ---------------------------------------------------------------------------
extern "C" void kernel_launch(void* const* d_in, const int* in_sizes, int n_in,
                              void* d_out, int out_size) {
    const float* x   = (const float*)d_in[0];
    const int*   rm  = (const int*)d_in[1];
    const float* Win = (const float*)d_in[2];
    const float* bin = (const float*)d_in[3];
    const float* Wgt = (const float*)d_in[4];
    const float* bgt = (const float*)d_in[5];
    const float* Wo  = (const float*)d_in[6];
    const float* bo  = (const float*)d_in[7];
    float* out = (float*)d_out;

    cudaFuncSetAttribute(gemm1_f16, cudaFuncAttributeMaxDynamicSharedMemorySize, 98304);
    cudaFuncSetAttribute(gemm2_f16, cudaFuncAttributeMaxDynamicSharedMemorySize, 98304);

    cvt_route_kernel<<<2049, 256>>>(Wgt, Win, Wo, x, rm);
    gemm1_f16<<<dim3(MAXT, HIDC / 64), 256, 98304>>>(bgt, bin);
    gemm2_f16<<<dim3(MAXT, DIMC / 128), 256, 98304>>>(bo, out);
}